// round 4
// baseline (speedup 1.0000x reference)
#include <cuda_runtime.h>
#include <cuda_bf16.h>
#include <cstdint>

#define R_TOTAL 32768   // B*N rows
#define KCODES  8192
#define DDIM    512
#define NTILES  512     // 16-wide code tiles for screening
#define MARGIN  7e-4f

// quantization scales
#define SZQ (127.0f / 6.0f)          // z scale
#define SEQ (127.0f * 8192.0f)       // embed scale
// 2 / (SZQ * SEQ), computed in double precision
#define INV2S ((float)(2.0 / ((127.0 / 6.0) * (127.0 * 8192.0))))

// ---------------- static scratch (no allocations allowed) ----------------
__device__ float  g_rowA[R_TOTAL];
__device__ float  g_enorm[KCODES];
__device__ float  g_rowpart[R_TOTAL];
__device__ int    g_codes[R_TOTAL];
__device__ int8_t g_zq[(size_t)R_TOTAL * DDIM];   // 16 MB
__device__ int8_t g_eq[(size_t)KCODES * DDIM];    //  4 MB
__device__ float  g_tilemin[(size_t)R_TOTAL * NTILES]; // 64 MB

__device__ __forceinline__ uint32_t smaddr(const void* p) {
    return (uint32_t)__cvta_generic_to_shared(p);
}
#define CP16(dst, src) \
    asm volatile("cp.async.cg.shared.global [%0], [%1], 16;" :: "r"(dst), "l"(src))
#define CP_COMMIT() asm volatile("cp.async.commit_group;")

// ---------------------------------------------------------------------------
// Row sum-of-squares (reference-exact NEON 4-lane emulation), z and embed in
// one launch. rows [0,32768) -> z, rows [32768,40960) -> embed.
// ---------------------------------------------------------------------------
__global__ void rownorm_kernel(const float* __restrict__ z,
                               const float* __restrict__ embed) {
    int gid  = blockIdx.x * blockDim.x + threadIdx.x;
    int row  = gid >> 2;
    int lane = gid & 3;
    if (row >= R_TOTAL + KCODES) return;
    const float* p = (row < R_TOTAL) ? (z + (size_t)row * DDIM)
                                     : (embed + (size_t)(row - R_TOTAL) * DDIM);
    float acc = 0.0f;
    #pragma unroll 8
    for (int i = lane; i < DDIM; i += 4) {
        float v = p[i];
        acc = __fadd_rn(acc, __fmul_rn(v, v));
    }
    float o  = __shfl_xor_sync(0xFFFFFFFF, acc, 2);
    float s  = __fadd_rn(acc, o);
    float o2 = __shfl_xor_sync(0xFFFFFFFF, s, 1);
    float A  = __fadd_rn(s, o2);
    if (lane == 0) {
        if (row < R_TOTAL) g_rowA[row] = A;
        else               g_enorm[row - R_TOTAL] = A;
    }
}

// ---------------------------------------------------------------------------
// fp32 -> int8 quantization. Thread handles 8 floats -> 8 int8 (uint2 store).
// ---------------------------------------------------------------------------
__device__ __forceinline__ uint32_t quant4(float4 v, float s) {
    int a = max(-127, min(127, __float2int_rn(v.x * s)));
    int b = max(-127, min(127, __float2int_rn(v.y * s)));
    int c = max(-127, min(127, __float2int_rn(v.z * s)));
    int d = max(-127, min(127, __float2int_rn(v.w * s)));
    return (uint32_t)(a & 255) | ((uint32_t)(b & 255) << 8) |
           ((uint32_t)(c & 255) << 16) | ((uint32_t)(d & 255) << 24);
}

__global__ void convert_kernel(const float* __restrict__ z,
                               const float* __restrict__ embed) {
    const int NZ8 = R_TOTAL * DDIM / 8;   // 2,097,152
    const int NE8 = KCODES * DDIM / 8;    //   524,288
    int i = blockIdx.x * blockDim.x + threadIdx.x;
    if (i < NZ8) {
        float4 v0 = ((const float4*)z)[i * 2];
        float4 v1 = ((const float4*)z)[i * 2 + 1];
        ((uint2*)g_zq)[i] = make_uint2(quant4(v0, SZQ), quant4(v1, SZQ));
    } else if (i < NZ8 + NE8) {
        int j = i - NZ8;
        float4 v0 = ((const float4*)embed)[j * 2];
        float4 v1 = ((const float4*)embed)[j * 2 + 1];
        ((uint2*)g_eq)[j] = make_uint2(quant4(v0, SEQ), quant4(v1, SEQ));
    }
}

// ---------------------------------------------------------------------------
// int8 screening GEMM: mma.sync.m16n8k32.s8, 128x128 tile, BK=64 int8,
// 3-stage cp.async pipeline (dynamic smem). Epilogue: per-(row, 16-code tile)
// min of approx dist -> g_tilemin.
// smem stage layout: A[128][80] then B[128][80] (80B row stride: ldmatrix
// phase pattern 5r+g mod 8 is conflict-free).
// ---------------------------------------------------------------------------
#define GBK       64
#define NKT       (DDIM / GBK)      // 8
#define ROWSTRIDE 80
#define HALF_ST   (128 * ROWSTRIDE) // 10240
#define STAGE_B   (2 * HALF_ST)     // 20480
#define NSTAGE    3
#define SM_TOTAL  (NSTAGE * STAGE_B)  // 61440

__global__ void __launch_bounds__(256, 2) screen_gemm_kernel() {
    extern __shared__ __align__(128) int8_t sm[];

    const int tid   = threadIdx.x;
    const int wid   = tid >> 5;
    const int lane  = tid & 31;
    const int warpY = wid >> 1;   // 0..3 : 32-row group
    const int warpX = wid & 1;    // 0..1 : 64-col group
    const int row0  = blockIdx.x * 128;
    const int n0    = blockIdx.y * 128;

    int acc[2][8][4];
    #pragma unroll
    for (int m = 0; m < 2; m++)
        #pragma unroll
        for (int n = 0; n < 8; n++)
            #pragma unroll
            for (int p = 0; p < 4; p++) acc[m][n][p] = 0;

    // chunk mapping: 512 16B-chunks per half; thread does chunks tid, tid+256
    const int ra = tid >> 2,        ga = (tid & 3) * 16;
    const int rb = (tid + 256) >> 2, gb = ((tid + 256) & 3) * 16;
    const int8_t* zsrc = g_zq + (size_t)row0 * DDIM;
    const int8_t* esrc = g_eq + (size_t)n0 * DDIM;

#define LOAD_TILE(kt) do {                                                    \
    int st_ = (kt) % NSTAGE;                                                  \
    int k0_ = (kt) * GBK;                                                     \
    uint32_t ab = smaddr(sm + st_ * STAGE_B);                                 \
    CP16(ab + ra * ROWSTRIDE + ga,           zsrc + (size_t)ra * DDIM + k0_ + ga); \
    CP16(ab + rb * ROWSTRIDE + gb,           zsrc + (size_t)rb * DDIM + k0_ + gb); \
    CP16(ab + HALF_ST + ra * ROWSTRIDE + ga, esrc + (size_t)ra * DDIM + k0_ + ga); \
    CP16(ab + HALF_ST + rb * ROWSTRIDE + gb, esrc + (size_t)rb * DDIM + k0_ + gb); \
    CP_COMMIT();                                                              \
} while (0)

    // ldmatrix per-thread addressing (byte units)
    const int i8 = lane & 7, q = lane >> 3;
    const int a_row = warpY * 32 + (q & 1) * 8 + i8;  // + m*16
    const int a_col = (q >> 1) * 16;                  // + ks*32
    const int b_row = warpX * 64 + i8;                // + n*8
    const int b_col = (q & 1) * 16;                   // + ks*32

    LOAD_TILE(0);
    LOAD_TILE(1);

    #pragma unroll 1
    for (int kt = 0; kt < NKT; kt++) {
        if (kt < NKT - 1) asm volatile("cp.async.wait_group 1;");
        else              asm volatile("cp.async.wait_group 0;");
        __syncthreads();
        if (kt + 2 < NKT) LOAD_TILE(kt + 2);   // overwrites stage (kt-1)%3: safe post-sync

        const uint32_t abase = smaddr(sm + (kt % NSTAGE) * STAGE_B);
        #pragma unroll
        for (int ks = 0; ks < 2; ks++) {
            uint32_t a[2][4], b[8][2];
            #pragma unroll
            for (int m = 0; m < 2; m++) {
                uint32_t addr = abase + (uint32_t)(a_row + m * 16) * ROWSTRIDE
                              + ks * 32 + a_col;
                asm volatile("ldmatrix.sync.aligned.m8n8.x4.shared.b16 {%0,%1,%2,%3}, [%4];"
                    : "=r"(a[m][0]), "=r"(a[m][1]), "=r"(a[m][2]), "=r"(a[m][3])
                    : "r"(addr));
            }
            #pragma unroll
            for (int n = 0; n < 8; n++) {
                uint32_t addr = abase + HALF_ST + (uint32_t)(b_row + n * 8) * ROWSTRIDE
                              + ks * 32 + b_col;
                asm volatile("ldmatrix.sync.aligned.m8n8.x2.shared.b16 {%0,%1}, [%2];"
                    : "=r"(b[n][0]), "=r"(b[n][1])
                    : "r"(addr));
            }
            #pragma unroll
            for (int m = 0; m < 2; m++)
                #pragma unroll
                for (int n = 0; n < 8; n++) {
                    asm volatile(
                        "mma.sync.aligned.m16n8k32.row.col.s32.s8.s8.s32 "
                        "{%0,%1,%2,%3}, {%4,%5,%6,%7}, {%8,%9}, {%0,%1,%2,%3};"
                        : "+r"(acc[m][n][0]), "+r"(acc[m][n][1]),
                          "+r"(acc[m][n][2]), "+r"(acc[m][n][3])
                        : "r"(a[m][0]), "r"(a[m][1]), "r"(a[m][2]), "r"(a[m][3]),
                          "r"(b[n][0]), "r"(b[n][1]));
                }
        }
    }
#undef LOAD_TILE

    // ---- epilogue: approx dist + per-(row, 16-code subtile) min ----
    const int g  = lane >> 2;   // row group 0..7
    const int qc = lane & 3;    // col pair

    float en[8][2];
    #pragma unroll
    for (int n = 0; n < 8; n++) {
        int col = n0 + warpX * 64 + n * 8 + qc * 2;
        en[n][0] = g_enorm[col];
        en[n][1] = g_enorm[col + 1];
    }

    #pragma unroll
    for (int m = 0; m < 2; m++) {
        #pragma unroll
        for (int h = 0; h < 2; h++) {
            int grow = row0 + warpY * 32 + m * 16 + g + h * 8;
            float Ar = g_rowA[grow];
            #pragma unroll
            for (int s = 0; s < 4; s++) {
                float v = 3.402823466e+38f;
                #pragma unroll
                for (int nn = 0; nn < 2; nn++) {
                    int n = s * 2 + nn;
                    #pragma unroll
                    for (int p = 0; p < 2; p++) {
                        float d = Ar - INV2S * (float)acc[m][n][h * 2 + p] + en[n][p];
                        v = fminf(v, d);
                    }
                }
                v = fminf(v, __shfl_xor_sync(0xFFFFFFFF, v, 1));
                v = fminf(v, __shfl_xor_sync(0xFFFFFFFF, v, 2));
                if (qc == 0)
                    g_tilemin[(size_t)grow * NTILES + blockIdx.y * 8 + warpX * 4 + s] = v;
            }
        }
    }
}

// ---------------------------------------------------------------------------
// Rescore: candidate tiles within MARGIN of screened min, recomputed with
// reference-exact fp32 rounding; lexicographic (val, idx) argmin.
// ---------------------------------------------------------------------------
__global__ void __launch_bounds__(256) rescore_kernel(
    const float* __restrict__ z,
    const float* __restrict__ embed,
    float* __restrict__ codes_f)
{
    __shared__ int cand[8][128];
    const int wid  = threadIdx.x >> 5;
    const int lane = threadIdx.x & 31;
    const int row  = blockIdx.x * 8 + wid;

    float tm[16];
    #pragma unroll
    for (int j = 0; j < 16; j++)
        tm[j] = g_tilemin[(size_t)row * NTILES + lane + 32 * j];

    float rmin = tm[0];
    #pragma unroll
    for (int j = 1; j < 16; j++) rmin = fminf(rmin, tm[j]);
    #pragma unroll
    for (int o = 16; o > 0; o >>= 1)
        rmin = fminf(rmin, __shfl_xor_sync(0xFFFFFFFF, rmin, o));

    const float thr = rmin + MARGIN;
    int cnt = 0;
    #pragma unroll
    for (int j = 0; j < 16; j++) {
        unsigned mask = __ballot_sync(0xFFFFFFFF, tm[j] <= thr);
        if ((mask >> lane) & 1) {
            int pos = cnt + __popc(mask & ((1u << lane) - 1));
            if (pos < 128) cand[wid][pos] = lane + 32 * j;
        }
        cnt += __popc(mask);
    }
    if (cnt > 128) cnt = 128;
    __syncwarp();

    const float A    = g_rowA[row];
    const float4* z4 = (const float4*)(z + (size_t)row * DDIM);
    float bestv = 3.402823466e+38f;
    int   besti = 0x7FFFFFFF;

    const int ncodes = cnt * 16;
    for (int p = 0; p * 32 < ncodes; p++) {
        int idx = p * 32 + lane;
        if (idx < ncodes) {
            int c = cand[wid][idx >> 4] * 16 + (idx & 15);
            const float4* e4 = (const float4*)(embed + (size_t)c * DDIM);
            float dot = 0.0f;
            #pragma unroll 8
            for (int k = 0; k < DDIM / 4; k++) {
                float4 ev = e4[k];
                float4 zv = z4[k];
                dot = fmaf(zv.x, ev.x, dot);
                dot = fmaf(zv.y, ev.y, dot);
                dot = fmaf(zv.z, ev.z, dot);
                dot = fmaf(zv.w, ev.w, dot);
            }
            float B2   = 2.0f * dot;
            float tt   = __fadd_rn(A, -B2);
            float dist = __fadd_rn(tt, g_enorm[c]);
            if (dist < bestv || (dist == bestv && c < besti)) {
                bestv = dist;
                besti = c;
            }
        }
    }

    #pragma unroll
    for (int o = 16; o > 0; o >>= 1) {
        float ov = __shfl_xor_sync(0xFFFFFFFF, bestv, o);
        int   oi = __shfl_xor_sync(0xFFFFFFFF, besti, o);
        if (ov < bestv || (ov == bestv && oi < besti)) { bestv = ov; besti = oi; }
    }
    if (lane == 0) {
        g_codes[row] = besti;
        if (codes_f) codes_f[row] = (float)besti;
    }
}

// ---------------------------------------------------------------------------
// Gather + loss (unchanged)
// ---------------------------------------------------------------------------
__global__ void gather_kernel(const float* __restrict__ z,
                              const float* __restrict__ embed,
                              float* __restrict__ out_zq) {
    const int row = blockIdx.x;
    const int t   = threadIdx.x;
    const int c   = g_codes[row];
    float4 e  = *(const float4*)(embed + (size_t)c * DDIM + t * 4);
    float4 zz = *(const float4*)(z + (size_t)row * DDIM + t * 4);
    *(float4*)(out_zq + (size_t)row * DDIM + t * 4) = e;
    float dx = zz.x - e.x, dy = zz.y - e.y, dz = zz.z - e.z, dw = zz.w - e.w;
    float s = dx * dx + dy * dy + dz * dz + dw * dw;
    __shared__ float red[128];
    red[t] = s;
    __syncthreads();
    #pragma unroll
    for (int o = 64; o > 0; o >>= 1) {
        if (t < o) red[t] += red[t + o];
        __syncthreads();
    }
    if (t == 0) g_rowpart[row] = red[0];
}

__global__ void loss_kernel(float* __restrict__ out_loss) {
    const int t = threadIdx.x;
    float s = 0.0f;
    for (int i = t; i < R_TOTAL; i += 1024) s += g_rowpart[i];
    __shared__ float red[1024];
    red[t] = s;
    __syncthreads();
    for (int o = 512; o > 0; o >>= 1) {
        if (t < o) red[t] += red[t + o];
        __syncthreads();
    }
    if (t == 0) out_loss[0] = 0.1f * (red[0] / 16777216.0f);
}

// ---------------------------------------------------------------------------
extern "C" void kernel_launch(void* const* d_in, const int* in_sizes, int n_in,
                              void* d_out, int out_size) {
    const float* z     = (const float*)d_in[0];   // (8,4096,512) f32
    const float* embed = (const float*)d_in[1];   // (8192,512) f32
    float* out = (float*)d_out;

    const long long ZQ_ELEMS = (long long)R_TOTAL * DDIM;
    float* out_zq    = out;
    float* out_codes = 0;
    float* out_loss  = 0;
    if ((long long)out_size >= ZQ_ELEMS + R_TOTAL + 1) {
        out_codes = out + ZQ_ELEMS;
        out_loss  = out + ZQ_ELEMS + R_TOTAL;
    }

    static int init_done = 0;
    if (!init_done) {
        cudaFuncSetAttribute(screen_gemm_kernel,
                             cudaFuncAttributeMaxDynamicSharedMemorySize, SM_TOTAL);
        init_done = 1;
    }

    const int NCONV = (R_TOTAL * DDIM + KCODES * DDIM) / 8;
    convert_kernel<<<(NCONV + 255) / 256, 256>>>(z, embed);

    rownorm_kernel<<<((R_TOTAL + KCODES) * 4 + 255) / 256, 256>>>(z, embed);

    dim3 gg(R_TOTAL / 128, KCODES / 128);   // (256, 64)
    screen_gemm_kernel<<<gg, 256, SM_TOTAL>>>();

    rescore_kernel<<<R_TOTAL / 8, 256>>>(z, embed, out_codes);

    gather_kernel<<<R_TOTAL, 128>>>(z, embed, out_zq);

    if (out_loss) loss_kernel<<<1, 1024>>>(out_loss);
}

// round 5
// speedup vs baseline: 2.1518x; 2.1518x over previous
#include <cuda_runtime.h>
#include <cuda_bf16.h>
#include <cstdint>

#define R_TOTAL 32768   // B*N rows
#define KCODES  8192
#define DDIM    512
#define NTILES  512     // 16-wide code tiles for screening
#define MARGIN  5e-4f

// ---------------- static scratch (no allocations allowed) ----------------
__device__ float         g_rowA[R_TOTAL];
__device__ float         g_enorm[KCODES];
__device__ float         g_rowpart[R_TOTAL];
__device__ int           g_codes[R_TOTAL];
__device__ __nv_bfloat16 g_zb[(size_t)R_TOTAL * DDIM];   // 32 MB
__device__ __nv_bfloat16 g_eb[(size_t)KCODES * DDIM];    //  8 MB
__device__ float         g_eT[(size_t)DDIM * KCODES];    // 16 MB  embed^T [k][code]
__device__ float         g_tilemin[(size_t)R_TOTAL * NTILES]; // 64 MB

__device__ __forceinline__ uint32_t smaddr(const void* p) {
    return (uint32_t)__cvta_generic_to_shared(p);
}
#define CP16(dst, src) \
    asm volatile("cp.async.cg.shared.global [%0], [%1], 16;" :: "r"(dst), "l"(src))
#define CP_COMMIT() asm volatile("cp.async.commit_group;")

// ---------------------------------------------------------------------------
// Row sum-of-squares (reference-exact NEON 4-lane emulation), z + embed fused.
// ---------------------------------------------------------------------------
__global__ void rownorm_kernel(const float* __restrict__ z,
                               const float* __restrict__ embed) {
    int gid  = blockIdx.x * blockDim.x + threadIdx.x;
    int row  = gid >> 2;
    int lane = gid & 3;
    if (row >= R_TOTAL + KCODES) return;
    const float* p = (row < R_TOTAL) ? (z + (size_t)row * DDIM)
                                     : (embed + (size_t)(row - R_TOTAL) * DDIM);
    float acc = 0.0f;
    #pragma unroll 8
    for (int i = lane; i < DDIM; i += 4) {
        float v = p[i];
        acc = __fadd_rn(acc, __fmul_rn(v, v));
    }
    float o  = __shfl_xor_sync(0xFFFFFFFF, acc, 2);
    float s  = __fadd_rn(acc, o);
    float o2 = __shfl_xor_sync(0xFFFFFFFF, s, 1);
    float A  = __fadd_rn(s, o2);
    if (lane == 0) {
        if (row < R_TOTAL) g_rowA[row] = A;
        else               g_enorm[row - R_TOTAL] = A;
    }
}

// ---------------------------------------------------------------------------
// fp32 -> bf16 conversion of z and embed
// ---------------------------------------------------------------------------
__global__ void convert_kernel(const float* __restrict__ z,
                               const float* __restrict__ embed) {
    const int NZ = R_TOTAL * DDIM / 4;
    const int NE = KCODES * DDIM / 4;
    int i = blockIdx.x * blockDim.x + threadIdx.x;
    if (i < NZ) {
        float4 v = ((const float4*)z)[i];
        ((__nv_bfloat162*)g_zb)[i * 2 + 0] = __floats2bfloat162_rn(v.x, v.y);
        ((__nv_bfloat162*)g_zb)[i * 2 + 1] = __floats2bfloat162_rn(v.z, v.w);
    } else if (i < NZ + NE) {
        int j = i - NZ;
        float4 v = ((const float4*)embed)[j];
        ((__nv_bfloat162*)g_eb)[j * 2 + 0] = __floats2bfloat162_rn(v.x, v.y);
        ((__nv_bfloat162*)g_eb)[j * 2 + 1] = __floats2bfloat162_rn(v.z, v.w);
    }
}

// ---------------------------------------------------------------------------
// embed (8192 x 512) -> embed_T (512 x 8192), fp32, smem tiled
// ---------------------------------------------------------------------------
__global__ void transpose_kernel(const float* __restrict__ embed) {
    __shared__ float t[32][33];
    const int bx = blockIdx.x * 32;   // k
    const int by = blockIdx.y * 32;   // code
    const int x = threadIdx.x, y = threadIdx.y;   // 32 x 8
    #pragma unroll
    for (int i = 0; i < 32; i += 8)
        t[y + i][x] = embed[(size_t)(by + y + i) * DDIM + bx + x];
    __syncthreads();
    #pragma unroll
    for (int i = 0; i < 32; i += 8)
        g_eT[(size_t)(bx + y + i) * KCODES + by + x] = t[x][y + i];
}

// ---------------------------------------------------------------------------
// Screening GEMM: bf16 mma.sync m16n8k16, 128x128 tile, GBK=32 bf16,
// 3-stage cp.async pipeline (one __syncthreads per kt), B via ldmatrix.x4.
// Epilogue: per-(row, 16-code tile) min of approx dist -> g_tilemin.
// Stage layout: A[128 rows][80 B] then B[128 rows][80 B]; 80-B row stride
// gives (5r + c) mod 8 conflict-free ldmatrix phases.
// ---------------------------------------------------------------------------
#define GBK       32                  // bf16 elements per chunk (64 B)
#define NKT       (DDIM / GBK)        // 16
#define ROWST     80
#define HALF_ST   (128 * ROWST)       // 10240
#define STAGE_B   (2 * HALF_ST)       // 20480
#define NSTAGE    3
#define SM_TOTAL  (NSTAGE * STAGE_B)  // 61440

__global__ void __launch_bounds__(256, 2) screen_gemm_kernel() {
    extern __shared__ __align__(128) char sm[];

    const int tid   = threadIdx.x;
    const int wid   = tid >> 5;
    const int lane  = tid & 31;
    const int warpY = wid >> 1;   // 0..3 : 32-row group
    const int warpX = wid & 1;    // 0..1 : 64-col group
    const int row0  = blockIdx.x * 128;
    const int n0    = blockIdx.y * 128;

    float acc[2][8][4];
    #pragma unroll
    for (int m = 0; m < 2; m++)
        #pragma unroll
        for (int n = 0; n < 8; n++)
            #pragma unroll
            for (int p = 0; p < 4; p++) acc[m][n][p] = 0.0f;

    // gmem->smem: 512 16-B chunks per half; thread does chunks tid, tid+256
    const int ra = tid >> 2,         gha = (tid & 3) * 8;          // halfwords
    const int rb = (tid + 256) >> 2, ghb = ((tid + 256) & 3) * 8;
    const __nv_bfloat16* zsrc = g_zb + (size_t)row0 * DDIM;
    const __nv_bfloat16* esrc = g_eb + (size_t)n0 * DDIM;

#define LOAD_TILE(kt) do {                                                     \
    int st_ = (kt) % NSTAGE;                                                   \
    int k0_ = (kt) * GBK;                                                      \
    uint32_t ab = smaddr(sm + st_ * STAGE_B);                                  \
    CP16(ab + ra * ROWST + gha * 2,           zsrc + (size_t)ra * DDIM + k0_ + gha); \
    CP16(ab + rb * ROWST + ghb * 2,           zsrc + (size_t)rb * DDIM + k0_ + ghb); \
    CP16(ab + HALF_ST + ra * ROWST + gha * 2, esrc + (size_t)ra * DDIM + k0_ + gha); \
    CP16(ab + HALF_ST + rb * ROWST + ghb * 2, esrc + (size_t)rb * DDIM + k0_ + ghb); \
    CP_COMMIT();                                                               \
} while (0)

    // ldmatrix addressing (byte units)
    const int i8 = lane & 7, q = lane >> 3;
    const int a_row  = warpY * 32 + (q & 1) * 8 + i8;   // + m*16
    const int a_colb = (q >> 1) * 16;                   // + ks*32
    const int b_row  = warpX * 64 + (q >> 1) * 8 + i8;  // + pair*16
    const int b_colb = (q & 1) * 16;                    // + ks*32

    LOAD_TILE(0);
    LOAD_TILE(1);

    #pragma unroll 1
    for (int kt = 0; kt < NKT; kt++) {
        if (kt < NKT - 1) asm volatile("cp.async.wait_group 1;");
        else              asm volatile("cp.async.wait_group 0;");
        __syncthreads();
        if (kt + 2 < NKT) LOAD_TILE(kt + 2);   // stage (kt-1)%3: consumed, safe

        const uint32_t abase = smaddr(sm + (kt % NSTAGE) * STAGE_B);
        #pragma unroll
        for (int ks = 0; ks < 2; ks++) {
            uint32_t a[2][4], b[4][4];
            #pragma unroll
            for (int m = 0; m < 2; m++) {
                uint32_t addr = abase + (uint32_t)(a_row + m * 16) * ROWST
                              + ks * 32 + a_colb;
                asm volatile("ldmatrix.sync.aligned.m8n8.x4.shared.b16 {%0,%1,%2,%3}, [%4];"
                    : "=r"(a[m][0]), "=r"(a[m][1]), "=r"(a[m][2]), "=r"(a[m][3])
                    : "r"(addr));
            }
            #pragma unroll
            for (int pr = 0; pr < 4; pr++) {
                uint32_t addr = abase + HALF_ST
                              + (uint32_t)(b_row + pr * 16) * ROWST
                              + ks * 32 + b_colb;
                asm volatile("ldmatrix.sync.aligned.m8n8.x4.shared.b16 {%0,%1,%2,%3}, [%4];"
                    : "=r"(b[pr][0]), "=r"(b[pr][1]), "=r"(b[pr][2]), "=r"(b[pr][3])
                    : "r"(addr));
            }
            #pragma unroll
            for (int m = 0; m < 2; m++)
                #pragma unroll
                for (int n = 0; n < 8; n++) {
                    const int pr = n >> 1, ro = (n & 1) * 2;
                    asm volatile(
                        "mma.sync.aligned.m16n8k16.row.col.f32.bf16.bf16.f32 "
                        "{%0,%1,%2,%3}, {%4,%5,%6,%7}, {%8,%9}, {%0,%1,%2,%3};"
                        : "+f"(acc[m][n][0]), "+f"(acc[m][n][1]),
                          "+f"(acc[m][n][2]), "+f"(acc[m][n][3])
                        : "r"(a[m][0]), "r"(a[m][1]), "r"(a[m][2]), "r"(a[m][3]),
                          "r"(b[pr][ro]), "r"(b[pr][ro + 1]));
                }
        }
    }
#undef LOAD_TILE

    // ---- epilogue: approx dist + per-(row, 16-code subtile) min ----
    const int g  = lane >> 2;   // row group 0..7
    const int qc = lane & 3;    // col pair

    float en[8][2];
    #pragma unroll
    for (int n = 0; n < 8; n++) {
        int col = n0 + warpX * 64 + n * 8 + qc * 2;
        en[n][0] = g_enorm[col];
        en[n][1] = g_enorm[col + 1];
    }

    #pragma unroll
    for (int m = 0; m < 2; m++) {
        #pragma unroll
        for (int h = 0; h < 2; h++) {
            int grow = row0 + warpY * 32 + m * 16 + g + h * 8;
            float Ar = g_rowA[grow];
            #pragma unroll
            for (int s = 0; s < 4; s++) {
                float v = 3.402823466e+38f;
                #pragma unroll
                for (int nn = 0; nn < 2; nn++) {
                    int n = s * 2 + nn;
                    #pragma unroll
                    for (int p = 0; p < 2; p++) {
                        float d = Ar - 2.0f * acc[m][n][h * 2 + p] + en[n][p];
                        v = fminf(v, d);
                    }
                }
                v = fminf(v, __shfl_xor_sync(0xFFFFFFFF, v, 1));
                v = fminf(v, __shfl_xor_sync(0xFFFFFFFF, v, 2));
                if (qc == 0)
                    g_tilemin[(size_t)grow * NTILES + blockIdx.y * 8 + warpX * 4 + s] = v;
            }
        }
    }
}

// ---------------------------------------------------------------------------
// Rescore v2: candidate tiles within MARGIN, recomputed bit-exactly via the
// TRANSPOSED codebook (16 consecutive codes per tile -> 64 B contiguous per k).
// One warp per row; half-warps process alternating candidate tiles.
// Dot = sequential ascending-k fmaf chain (identical rounding to reference
// emulation); lexicographic (val, idx) argmin.
// ---------------------------------------------------------------------------
__global__ void __launch_bounds__(256) rescore_kernel(
    const float* __restrict__ z,
    float* __restrict__ codes_f)
{
    __shared__ float zs[8][DDIM];
    __shared__ int   cand[8][64];
    const int wid  = threadIdx.x >> 5;
    const int lane = threadIdx.x & 31;
    const int row  = blockIdx.x * 8 + wid;

    // stage z row (coalesced; broadcast-read later)
    {
        const float4* z4 = (const float4*)(z + (size_t)row * DDIM);
        float4* s4 = (float4*)zs[wid];
        #pragma unroll
        for (int i = lane; i < DDIM / 4; i += 32) s4[i] = z4[i];
    }

    float tm[16];
    #pragma unroll
    for (int j = 0; j < 16; j++)
        tm[j] = g_tilemin[(size_t)row * NTILES + lane + 32 * j];

    float rmin = tm[0];
    #pragma unroll
    for (int j = 1; j < 16; j++) rmin = fminf(rmin, tm[j]);
    #pragma unroll
    for (int o = 16; o > 0; o >>= 1)
        rmin = fminf(rmin, __shfl_xor_sync(0xFFFFFFFF, rmin, o));

    const float thr = rmin + MARGIN;
    int cnt = 0;
    #pragma unroll
    for (int j = 0; j < 16; j++) {
        unsigned mask = __ballot_sync(0xFFFFFFFF, tm[j] <= thr);
        if ((mask >> lane) & 1) {
            int pos = cnt + __popc(mask & ((1u << lane) - 1));
            if (pos < 64) cand[wid][pos] = lane + 32 * j;
        }
        cnt += __popc(mask);
    }
    if (cnt > 64) cnt = 64;
    __syncwarp();

    const float A    = g_rowA[row];
    const int   half = lane >> 4;    // 0/1: alternating tiles
    const int   l16  = lane & 15;
    const float* zr  = zs[wid];

    float bestv = 3.402823466e+38f;
    int   besti = 0x7FFFFFFF;

    for (int t = half; t < cnt; t += 2) {
        const int c = cand[wid][t] * 16 + l16;
        const float* ec = g_eT + c;
        float dot = 0.0f;
        #pragma unroll 8
        for (int k = 0; k < DDIM; k++)
            dot = fmaf(zr[k], ec[(size_t)k * KCODES], dot);
        float B2   = 2.0f * dot;
        float tt   = __fadd_rn(A, -B2);
        float dist = __fadd_rn(tt, g_enorm[c]);
        if (dist < bestv || (dist == bestv && c < besti)) {
            bestv = dist;
            besti = c;
        }
    }

    #pragma unroll
    for (int o = 16; o > 0; o >>= 1) {
        float ov = __shfl_xor_sync(0xFFFFFFFF, bestv, o);
        int   oi = __shfl_xor_sync(0xFFFFFFFF, besti, o);
        if (ov < bestv || (ov == bestv && oi < besti)) { bestv = ov; besti = oi; }
    }
    if (lane == 0) {
        g_codes[row] = besti;
        if (codes_f) codes_f[row] = (float)besti;
    }
}

// ---------------------------------------------------------------------------
// Gather + loss (unchanged, proven)
// ---------------------------------------------------------------------------
__global__ void gather_kernel(const float* __restrict__ z,
                              const float* __restrict__ embed,
                              float* __restrict__ out_zq) {
    const int row = blockIdx.x;
    const int t   = threadIdx.x;
    const int c   = g_codes[row];
    float4 e  = *(const float4*)(embed + (size_t)c * DDIM + t * 4);
    float4 zz = *(const float4*)(z + (size_t)row * DDIM + t * 4);
    *(float4*)(out_zq + (size_t)row * DDIM + t * 4) = e;
    float dx = zz.x - e.x, dy = zz.y - e.y, dz = zz.z - e.z, dw = zz.w - e.w;
    float s = dx * dx + dy * dy + dz * dz + dw * dw;
    __shared__ float red[128];
    red[t] = s;
    __syncthreads();
    #pragma unroll
    for (int o = 64; o > 0; o >>= 1) {
        if (t < o) red[t] += red[t + o];
        __syncthreads();
    }
    if (t == 0) g_rowpart[row] = red[0];
}

__global__ void loss_kernel(float* __restrict__ out_loss) {
    const int t = threadIdx.x;
    float s = 0.0f;
    for (int i = t; i < R_TOTAL; i += 1024) s += g_rowpart[i];
    __shared__ float red[1024];
    red[t] = s;
    __syncthreads();
    for (int o = 512; o > 0; o >>= 1) {
        if (t < o) red[t] += red[t + o];
        __syncthreads();
    }
    if (t == 0) out_loss[0] = 0.1f * (red[0] / 16777216.0f);
}

// ---------------------------------------------------------------------------
extern "C" void kernel_launch(void* const* d_in, const int* in_sizes, int n_in,
                              void* d_out, int out_size) {
    const float* z     = (const float*)d_in[0];   // (8,4096,512) f32
    const float* embed = (const float*)d_in[1];   // (8192,512) f32
    float* out = (float*)d_out;

    const long long ZQ_ELEMS = (long long)R_TOTAL * DDIM;
    float* out_zq    = out;
    float* out_codes = 0;
    float* out_loss  = 0;
    if ((long long)out_size >= ZQ_ELEMS + R_TOTAL + 1) {
        out_codes = out + ZQ_ELEMS;
        out_loss  = out + ZQ_ELEMS + R_TOTAL;
    }

    static int init_done = 0;
    if (!init_done) {
        cudaFuncSetAttribute(screen_gemm_kernel,
                             cudaFuncAttributeMaxDynamicSharedMemorySize, SM_TOTAL);
        init_done = 1;
    }

    const int NCONV = (R_TOTAL * DDIM + KCODES * DDIM) / 4;
    convert_kernel<<<(NCONV + 255) / 256, 256>>>(z, embed);

    rownorm_kernel<<<((R_TOTAL + KCODES) * 4 + 255) / 256, 256>>>(z, embed);

    transpose_kernel<<<dim3(DDIM / 32, KCODES / 32), dim3(32, 8)>>>(embed);

    dim3 gg(R_TOTAL / 128, KCODES / 128);   // (256, 64)
    screen_gemm_kernel<<<gg, 256, SM_TOTAL>>>();

    rescore_kernel<<<R_TOTAL / 8, 256>>>(z, out_codes);

    gather_kernel<<<R_TOTAL, 128>>>(z, embed, out_zq);

    if (out_loss) loss_kernel<<<1, 1024>>>(out_loss);
}